// round 5
// baseline (speedup 1.0000x reference)
#include <cuda_runtime.h>
#include <math.h>
#include <stdint.h>

#define D_DIM    4096
#define E_DIM    64
#define TOPK     8
#define TILE_M   128
#define BK       16
#define NCH      (D_DIM / BK)       // 256 chunks of 16
#define NTHREADS 256

// smem layout (bytes)
// XT: [2 buf][16 k][128 row] f32      -> 2 * 8192
// BD: [2 buf][16 k][64 e dup f32x2]   -> 2 * 8192
// scratch (epilogue, reuses 0..33280): 128 * 65 * 4
// RS: rowsum, placed after scratch
#define XT_OFF   0
#define BD_OFF   16384
#define RS_OFF   33280
#define SMEM_DYN (RS_OFF + 512)

static __device__ __forceinline__ uint32_t smem_u32(const void* p) {
    uint32_t a;
    asm("{ .reg .u64 t; cvta.to.shared.u64 t, %1; cvt.u32.u64 %0, t; }" : "=r"(a) : "l"(p));
    return a;
}

static __device__ __forceinline__ void lds_v2u64(uint32_t addr,
                                                 unsigned long long& a,
                                                 unsigned long long& b) {
    asm volatile("ld.shared.v2.b64 {%0,%1}, [%2];" : "=l"(a), "=l"(b) : "r"(addr));
}

static __device__ __forceinline__ void fma2(unsigned long long& d,
                                            unsigned long long a,
                                            unsigned long long b) {
    asm("fma.rn.f32x2 %0, %1, %2, %0;" : "+l"(d) : "l"(a), "l"(b));
}

static __device__ __forceinline__ float softplus_f(float v) {
    return fmaxf(v, 0.f) + log1pf(expf(-fabsf(v)));
}

__global__ __launch_bounds__(NTHREADS, 1)
void router_f32x2_kernel(const float* __restrict__ x,
                         const float* __restrict__ sig,
                         float* __restrict__ out_w,
                         float* __restrict__ out_i,
                         float* __restrict__ out_res)
{
    extern __shared__ char sm[];
    const uint32_t sb = smem_u32(sm);

    const int tid = threadIdx.x;
    const int ex  = tid & 15;        // expert group: experts ex*4 .. +3
    const int ey  = tid >> 4;        // row group: rows ey*8 .. +7
    const int row0 = blockIdx.x * TILE_M;

    // loader coords
    const int lrow = tid & 127;      // x loader row
    const int lkq0 = tid >> 7;       // 0 or 1 -> kq = lkq0 + 2*i
    const int le   = tid & 63;       // sig loader expert
    const int lkqs = tid >> 6;       // 0..3

    // accumulators: acc[p][j] = { rows ey*8+2p , ey*8+2p+1 } x expert ex*4+j
    unsigned long long acc[4][4];
#pragma unroll
    for (int p = 0; p < 4; p++)
#pragma unroll
        for (int j = 0; j < 4; j++) acc[p][j] = 0ull;

    float ss = 0.f;  // serial ascending sum of squares (threads < 128, row = tid)

    const float4* xq = (const float4*)x + (size_t)row0 * (D_DIM / 4);
    const float4* sq = (const float4*)sig;

    // prologue: load chunk 0 into regs
    float4 xv[2], svv;
#pragma unroll
    for (int i = 0; i < 2; i++)
        xv[i] = xq[(size_t)lrow * (D_DIM / 4) + (lkq0 + 2 * i)];
    svv = sq[(size_t)le * (D_DIM / 4) + lkqs];

    for (int kc = 0; kc < NCH; kc++) {
        const int buf = kc & 1;

        // ---- store regs -> smem (x transposed, sig duplicated) ----
        {
            float* xt = (float*)(sm + XT_OFF + buf * 8192);
#pragma unroll
            for (int i = 0; i < 2; i++) {
                const int kq = lkq0 + 2 * i;
                xt[(kq * 4 + 0) * 128 + lrow] = xv[i].x;
                xt[(kq * 4 + 1) * 128 + lrow] = xv[i].y;
                xt[(kq * 4 + 2) * 128 + lrow] = xv[i].z;
                xt[(kq * 4 + 3) * 128 + lrow] = xv[i].w;
            }
            float2* bd = (float2*)(sm + BD_OFF + buf * 8192);
            bd[(lkqs * 4 + 0) * 64 + le] = make_float2(svv.x, svv.x);
            bd[(lkqs * 4 + 1) * 64 + le] = make_float2(svv.y, svv.y);
            bd[(lkqs * 4 + 2) * 64 + le] = make_float2(svv.z, svv.z);
            bd[(lkqs * 4 + 3) * 64 + le] = make_float2(svv.w, svv.w);
        }
        __syncthreads();

        // ---- prefetch next chunk ----
        if (kc + 1 < NCH) {
#pragma unroll
            for (int i = 0; i < 2; i++)
                xv[i] = xq[(size_t)lrow * (D_DIM / 4) + (kc + 1) * 4 + (lkq0 + 2 * i)];
            svv = sq[(size_t)le * (D_DIM / 4) + (kc + 1) * 4 + lkqs];
        }

        // ---- compute ----
        {
            const uint32_t ap = sb + XT_OFF + buf * 8192 + ey * 32;
            const uint32_t bp = sb + BD_OFF + buf * 8192 + ex * 32;
#pragma unroll
            for (int k = 0; k < BK; k++) {
                unsigned long long a01, a23, a45, a67, b0, b1, b2, b3;
                lds_v2u64(ap + k * 512,      a01, a23);
                lds_v2u64(ap + k * 512 + 16, a45, a67);
                lds_v2u64(bp + k * 512,      b0, b1);
                lds_v2u64(bp + k * 512 + 16, b2, b3);
                fma2(acc[0][0], a01, b0); fma2(acc[0][1], a01, b1);
                fma2(acc[0][2], a01, b2); fma2(acc[0][3], a01, b3);
                fma2(acc[1][0], a23, b0); fma2(acc[1][1], a23, b1);
                fma2(acc[1][2], a23, b2); fma2(acc[1][3], a23, b3);
                fma2(acc[2][0], a45, b0); fma2(acc[2][1], a45, b1);
                fma2(acc[2][2], a45, b2); fma2(acc[2][3], a45, b3);
                fma2(acc[3][0], a67, b0); fma2(acc[3][1], a67, b1);
                fma2(acc[3][2], a67, b2); fma2(acc[3][3], a67, b3);
            }
            // serial ascending sumsq for row = tid (threads 0..127)
            if (tid < TILE_M) {
                const float* xt = (const float*)(sm + XT_OFF + buf * 8192);
#pragma unroll
                for (int k = 0; k < BK; k++) {
                    float a = xt[k * 128 + tid];
                    ss = fmaf(a, a, ss);
                }
            }
        }
        __syncthreads();
    }

    // ---- rowsum / inv-norm (R1-identical expressions) ----
    float* rowsum = (float*)(sm + RS_OFF);
    if (tid < TILE_M) {
        float nrm = fmaxf(sqrtf(ss), 1e-12f);
        rowsum[tid] = 1.f / nrm;      // inv norm
    }
    __syncthreads();

    // ---- scale, write resonance, stash scaled rows in scratch ----
    float* scr = (float*)sm;          // [128][65]
#pragma unroll
    for (int p = 0; p < 4; p++) {
        const int r0 = ey * 8 + 2 * p;
        const int r1 = r0 + 1;
        const float s0 = 5.0f * rowsum[r0];
        const float s1 = 5.0f * rowsum[r1];
        float lo[4], hi[4];
#pragma unroll
        for (int j = 0; j < 4; j++) {
            unsigned long long u = acc[p][j];
            lo[j] = __uint_as_float((uint32_t)u) * s0;
            hi[j] = __uint_as_float((uint32_t)(u >> 32)) * s1;
        }
        *(float4*)(out_res + (size_t)(row0 + r0) * E_DIM + ex * 4) =
            make_float4(lo[0], lo[1], lo[2], lo[3]);
        *(float4*)(out_res + (size_t)(row0 + r1) * E_DIM + ex * 4) =
            make_float4(hi[0], hi[1], hi[2], hi[3]);
#pragma unroll
        for (int j = 0; j < 4; j++) {
            scr[r0 * 65 + ex * 4 + j] = lo[j];
            scr[r1 * 65 + ex * 4 + j] = hi[j];
        }
    }
    __syncthreads();

    // ---- fused top-8 + softplus (threads 0..127, one row each) ----
    if (tid < TILE_M) {
        float vals[64];
#pragma unroll
        for (int c = 0; c < 64; c++) vals[c] = scr[tid * 65 + c];
        float* wp = out_w + (size_t)(row0 + tid) * TOPK;
        float* ip = out_i + (size_t)(row0 + tid) * TOPK;
#pragma unroll
        for (int it = 0; it < TOPK; it++) {
            float best = vals[0];
            int bi = 0;
#pragma unroll
            for (int c = 1; c < 64; c++) {
                if (vals[c] > best) { best = vals[c]; bi = c; }
            }
            vals[bi] = -INFINITY;
            wp[it] = softplus_f(best);
            ip[it] = (float)bi;
        }
    }
}

extern "C" void kernel_launch(void* const* d_in, const int* in_sizes, int n_in,
                              void* d_out, int out_size)
{
    const float* x   = (const float*)d_in[0];
    const float* sig = (const float*)d_in[1];
    const int n_rows = in_sizes[0] / D_DIM;   // 16384

    float* out = (float*)d_out;
    float* out_w   = out;
    float* out_i   = out + (size_t)n_rows * TOPK;
    float* out_res = out + (size_t)n_rows * TOPK * 2;

    cudaFuncSetAttribute(router_f32x2_kernel,
                         cudaFuncAttributeMaxDynamicSharedMemorySize, SMEM_DYN);

    router_f32x2_kernel<<<n_rows / TILE_M, NTHREADS, SMEM_DYN>>>(
        x, sig, out_w, out_i, out_res);
}

// round 6
// speedup vs baseline: 1.0894x; 1.0894x over previous
#include <cuda_runtime.h>
#include <math.h>
#include <stdint.h>

#define D_DIM    4096
#define E_DIM    64
#define TOPK     8
#define TILE_M   128
#define BK       32
#define NCH      (D_DIM / BK)       // 128 chunks of 32
#define NTHREADS 512

// smem layout (bytes)
// XT: [2 buf][32 k][128 row] f32        -> 2 * 16384
// BD: [2 buf][32 k][64 e dup f32x2]     -> 2 * 16384
// scratch (epilogue) reuses [0, 33280) ; RS after buffers
#define XT_OFF   0
#define BD_OFF   32768
#define RS_OFF   65536
#define SMEM_DYN (RS_OFF + 512)

static __device__ __forceinline__ uint32_t smem_u32(const void* p) {
    uint32_t a;
    asm("{ .reg .u64 t; cvta.to.shared.u64 t, %1; cvt.u32.u64 %0, t; }" : "=r"(a) : "l"(p));
    return a;
}

static __device__ __forceinline__ void lds_v2u64(uint32_t addr,
                                                 unsigned long long& a,
                                                 unsigned long long& b) {
    asm volatile("ld.shared.v2.b64 {%0,%1}, [%2];" : "=l"(a), "=l"(b) : "r"(addr));
}

static __device__ __forceinline__ void fma2(unsigned long long& d,
                                            unsigned long long a,
                                            unsigned long long b) {
    asm("fma.rn.f32x2 %0, %1, %2, %0;" : "+l"(d) : "l"(a), "l"(b));
}

static __device__ __forceinline__ float softplus_f(float v) {
    return fmaxf(v, 0.f) + log1pf(expf(-fabsf(v)));
}

__global__ __launch_bounds__(NTHREADS, 1)
void router_f32x2_v2_kernel(const float* __restrict__ x,
                            const float* __restrict__ sig,
                            float* __restrict__ out_w,
                            float* __restrict__ out_i,
                            float* __restrict__ out_res)
{
    extern __shared__ char sm[];
    const uint32_t sb = smem_u32(sm);

    const int tid  = threadIdx.x;
    const int wid  = tid >> 5;
    const int lane = tid & 31;
    const int wy   = wid & 3;          // warp row band (32 rows)
    const int wx   = wid >> 2;         // warp expert band (16 experts)
    const int ey   = lane & 7;         // 8 row-groups of 4 rows
    const int ex   = lane >> 3;        // 4 expert-groups of 4 experts
    const int r0   = wy * 32 + ey * 4; // first of 4 rows
    const int e0   = wx * 16 + ex * 4; // first of 4 experts
    const int row0 = blockIdx.x * TILE_M;

    // loader coords
    const int lrow = tid & 127;        // x loader row
    const int lkq  = tid >> 7;         // 0..3 -> float4 slots lkq, lkq+4
    const int le   = tid & 63;         // sig loader expert
    const int lkqs = tid >> 6;         // 0..7

    // acc[p][j]: rows (r0+2p, r0+2p+1) x expert (e0+j), packed f32x2
    unsigned long long acc[2][4];
#pragma unroll
    for (int p = 0; p < 2; p++)
#pragma unroll
        for (int j = 0; j < 4; j++) acc[p][j] = 0ull;

    float ss = 0.f;   // serial ascending sumsq, row = tid (threads < 128)

    const float4* xq = (const float4*)x + (size_t)row0 * (D_DIM / 4);
    const float4* sq = (const float4*)sig;

    // prologue: chunk 0 loads
    float4 xv[2], svv;
    xv[0] = xq[(size_t)lrow * (D_DIM / 4) + lkq];
    xv[1] = xq[(size_t)lrow * (D_DIM / 4) + lkq + 4];
    svv   = sq[(size_t)le * (D_DIM / 4) + lkqs];

    for (int kc = 0; kc < NCH; kc++) {
        const int buf = kc & 1;

        // ---- store regs -> smem (x transposed, sig duplicated) ----
        {
            float* xt = (float*)(sm + XT_OFF + buf * 16384);
#pragma unroll
            for (int i = 0; i < 2; i++) {
                const int kq = lkq + 4 * i;
                xt[(kq * 4 + 0) * 128 + lrow] = xv[i].x;
                xt[(kq * 4 + 1) * 128 + lrow] = xv[i].y;
                xt[(kq * 4 + 2) * 128 + lrow] = xv[i].z;
                xt[(kq * 4 + 3) * 128 + lrow] = xv[i].w;
            }
            float2* bd = (float2*)(sm + BD_OFF + buf * 16384);
            bd[(lkqs * 4 + 0) * 64 + le] = make_float2(svv.x, svv.x);
            bd[(lkqs * 4 + 1) * 64 + le] = make_float2(svv.y, svv.y);
            bd[(lkqs * 4 + 2) * 64 + le] = make_float2(svv.z, svv.z);
            bd[(lkqs * 4 + 3) * 64 + le] = make_float2(svv.w, svv.w);
        }
        __syncthreads();

        // ---- prefetch next chunk ----
        if (kc + 1 < NCH) {
            xv[0] = xq[(size_t)lrow * (D_DIM / 4) + (kc + 1) * 8 + lkq];
            xv[1] = xq[(size_t)lrow * (D_DIM / 4) + (kc + 1) * 8 + lkq + 4];
            svv   = sq[(size_t)le * (D_DIM / 4) + (kc + 1) * 8 + lkqs];
        }

        // ---- compute: 32 k-steps, 3 LDS + 8 FMA2 each ----
        {
            const uint32_t ap = sb + XT_OFF + buf * 16384 + (uint32_t)r0 * 4;
            const uint32_t bp = sb + BD_OFF + buf * 16384 + (uint32_t)e0 * 8;
#pragma unroll
            for (int k = 0; k < BK; k++) {
                unsigned long long a01, a23, b0, b1, b2, b3;
                lds_v2u64(ap + k * 512, a01, a23);
                lds_v2u64(bp + k * 512, b0, b1);
                lds_v2u64(bp + k * 512 + 16, b2, b3);
                fma2(acc[0][0], a01, b0); fma2(acc[0][1], a01, b1);
                fma2(acc[0][2], a01, b2); fma2(acc[0][3], a01, b3);
                fma2(acc[1][0], a23, b0); fma2(acc[1][1], a23, b1);
                fma2(acc[1][2], a23, b2); fma2(acc[1][3], a23, b3);
            }
            // serial ascending sumsq for row = tid (threads 0..127)
            if (tid < TILE_M) {
                const float* xt = (const float*)(sm + XT_OFF + buf * 16384);
#pragma unroll
                for (int k = 0; k < BK; k++) {
                    float a = xt[k * 128 + tid];
                    ss = fmaf(a, a, ss);
                }
            }
        }
        __syncthreads();
    }

    // ---- inv norm (R1-identical expressions) ----
    float* rowsum = (float*)(sm + RS_OFF);
    if (tid < TILE_M) {
        float nrm = fmaxf(sqrtf(ss), 1e-12f);
        rowsum[tid] = 1.f / nrm;
    }
    __syncthreads();

    // ---- scale, write resonance, stash scaled rows in scratch ----
    float* scr = (float*)sm;     // [128][65]
#pragma unroll
    for (int p = 0; p < 2; p++) {
        const int ra = r0 + 2 * p;
        const int rb = ra + 1;
        const float s0 = 5.0f * rowsum[ra];
        const float s1 = 5.0f * rowsum[rb];
        float lo[4], hi[4];
#pragma unroll
        for (int j = 0; j < 4; j++) {
            unsigned long long u = acc[p][j];
            lo[j] = __uint_as_float((uint32_t)u) * s0;
            hi[j] = __uint_as_float((uint32_t)(u >> 32)) * s1;
        }
        *(float4*)(out_res + (size_t)(row0 + ra) * E_DIM + e0) =
            make_float4(lo[0], lo[1], lo[2], lo[3]);
        *(float4*)(out_res + (size_t)(row0 + rb) * E_DIM + e0) =
            make_float4(hi[0], hi[1], hi[2], hi[3]);
#pragma unroll
        for (int j = 0; j < 4; j++) {
            scr[ra * 65 + e0 + j] = lo[j];
            scr[rb * 65 + e0 + j] = hi[j];
        }
    }
    __syncthreads();

    // ---- fused top-8 + softplus (threads 0..127, one row each) ----
    if (tid < TILE_M) {
        float vals[64];
#pragma unroll
        for (int c = 0; c < 64; c++) vals[c] = scr[tid * 65 + c];
        float* wp = out_w + (size_t)(row0 + tid) * TOPK;
        float* ip = out_i + (size_t)(row0 + tid) * TOPK;
#pragma unroll
        for (int it = 0; it < TOPK; it++) {
            float best = vals[0];
            int bi = 0;
#pragma unroll
            for (int c = 1; c < 64; c++) {
                if (vals[c] > best) { best = vals[c]; bi = c; }
            }
            vals[bi] = -INFINITY;
            wp[it] = softplus_f(best);
            ip[it] = (float)bi;
        }
    }
}

extern "C" void kernel_launch(void* const* d_in, const int* in_sizes, int n_in,
                              void* d_out, int out_size)
{
    const float* x   = (const float*)d_in[0];
    const float* sig = (const float*)d_in[1];
    const int n_rows = in_sizes[0] / D_DIM;   // 16384

    float* out = (float*)d_out;
    float* out_w   = out;
    float* out_i   = out + (size_t)n_rows * TOPK;
    float* out_res = out + (size_t)n_rows * TOPK * 2;

    cudaFuncSetAttribute(router_f32x2_v2_kernel,
                         cudaFuncAttributeMaxDynamicSharedMemorySize, SMEM_DYN);

    router_f32x2_v2_kernel<<<n_rows / TILE_M, NTHREADS, SMEM_DYN>>>(
        x, sig, out_w, out_i, out_res);
}

// round 7
// speedup vs baseline: 1.1024x; 1.0119x over previous
#include <cuda_runtime.h>
#include <math.h>
#include <stdint.h>

#define D_DIM    4096
#define E_DIM    64
#define TOPK     8
#define TILE_M   64
#define BK       32
#define NCH      (D_DIM / BK)       // 128 chunks of 32
#define NTHREADS 256

// smem layout (bytes)
// XT: [2 buf][32 k][64 row] f32        -> 2 * 8192
// BD: [2 buf][32 k][64 e dup f32x2]    -> 2 * 16384
// PS: partial sumsq [4][64] f32        -> 1024
// RS: inv-norm [64] f32
#define XT_OFF   0
#define BD_OFF   16384
#define PS_OFF   49152
#define RS_OFF   50176
#define SMEM_DYN 50688
// epilogue scratch (64*65*4 = 16640 B) reuses [0, XT+BD region)

static __device__ __forceinline__ uint32_t smem_u32(const void* p) {
    uint32_t a;
    asm("{ .reg .u64 t; cvta.to.shared.u64 t, %1; cvt.u32.u64 %0, t; }" : "=r"(a) : "l"(p));
    return a;
}

static __device__ __forceinline__ void lds_v2u64(uint32_t addr,
                                                 unsigned long long& a,
                                                 unsigned long long& b) {
    asm volatile("ld.shared.v2.b64 {%0,%1}, [%2];" : "=l"(a), "=l"(b) : "r"(addr));
}

static __device__ __forceinline__ void fma2(unsigned long long& d,
                                            unsigned long long a,
                                            unsigned long long b) {
    asm("fma.rn.f32x2 %0, %1, %2, %0;" : "+l"(d) : "l"(a), "l"(b));
}

static __device__ __forceinline__ float softplus_f(float v) {
    return fmaxf(v, 0.f) + log1pf(expf(-fabsf(v)));
}

__global__ __launch_bounds__(NTHREADS, 3)
void router_f32x2_v3_kernel(const float* __restrict__ x,
                            const float* __restrict__ sig,
                            float* __restrict__ out_w,
                            float* __restrict__ out_i,
                            float* __restrict__ out_res)
{
    extern __shared__ char sm[];
    const uint32_t sb = smem_u32(sm);

    const int tid  = threadIdx.x;
    const int wid  = tid >> 5;
    const int lane = tid & 31;
    const int wy   = wid & 1;          // row band (32 rows)
    const int wx   = wid >> 1;         // expert band (16 experts)
    const int ey   = lane & 7;
    const int ex   = lane >> 3;
    const int r0   = wy * 32 + ey * 4; // 4 rows
    const int e0   = wx * 16 + ex * 4; // 4 experts
    const int row0 = blockIdx.x * TILE_M;

    // loader coords: 64 rows x 8 float4-slots per chunk; thread covers slots lkq, lkq+4
    const int lrow = tid & 63;
    const int lkq  = tid >> 6;         // 0..3

    // acc[p][j]: rows (r0+2p, r0+2p+1) x expert (e0+j), packed f32x2
    unsigned long long acc[2][4];
#pragma unroll
    for (int p = 0; p < 2; p++)
#pragma unroll
        for (int j = 0; j < 4; j++) acc[p][j] = 0ull;

    float ss = 0.f;   // partial sumsq for row lrow (slots lkq, lkq+4 of each chunk)

    const float4* xq = (const float4*)x + (size_t)(row0 + lrow) * (D_DIM / 4);
    const float4* sq = (const float4*)sig + (size_t)lrow * (D_DIM / 4);

    // prologue: chunk 0
    float4 xv0 = xq[lkq];
    float4 xv1 = xq[lkq + 4];
    float4 sv0 = sq[lkq];
    float4 sv1 = sq[lkq + 4];

    for (int kc = 0; kc < NCH; kc++) {
        const int buf = kc & 1;

        // ---- store regs -> smem; fold sumsq from registers ----
        {
            float* xt = (float*)(sm + XT_OFF + buf * 8192);
            xt[((lkq * 4) + 0) * 64 + lrow] = xv0.x;
            xt[((lkq * 4) + 1) * 64 + lrow] = xv0.y;
            xt[((lkq * 4) + 2) * 64 + lrow] = xv0.z;
            xt[((lkq * 4) + 3) * 64 + lrow] = xv0.w;
            xt[((lkq * 4) + 16) * 64 + lrow] = xv1.x;
            xt[((lkq * 4) + 17) * 64 + lrow] = xv1.y;
            xt[((lkq * 4) + 18) * 64 + lrow] = xv1.z;
            xt[((lkq * 4) + 19) * 64 + lrow] = xv1.w;
            ss = fmaf(xv0.x, xv0.x, ss); ss = fmaf(xv0.y, xv0.y, ss);
            ss = fmaf(xv0.z, xv0.z, ss); ss = fmaf(xv0.w, xv0.w, ss);
            ss = fmaf(xv1.x, xv1.x, ss); ss = fmaf(xv1.y, xv1.y, ss);
            ss = fmaf(xv1.z, xv1.z, ss); ss = fmaf(xv1.w, xv1.w, ss);

            float2* bd = (float2*)(sm + BD_OFF + buf * 16384);
            bd[((lkq * 4) + 0) * 64 + lrow] = make_float2(sv0.x, sv0.x);
            bd[((lkq * 4) + 1) * 64 + lrow] = make_float2(sv0.y, sv0.y);
            bd[((lkq * 4) + 2) * 64 + lrow] = make_float2(sv0.z, sv0.z);
            bd[((lkq * 4) + 3) * 64 + lrow] = make_float2(sv0.w, sv0.w);
            bd[((lkq * 4) + 16) * 64 + lrow] = make_float2(sv1.x, sv1.x);
            bd[((lkq * 4) + 17) * 64 + lrow] = make_float2(sv1.y, sv1.y);
            bd[((lkq * 4) + 18) * 64 + lrow] = make_float2(sv1.z, sv1.z);
            bd[((lkq * 4) + 19) * 64 + lrow] = make_float2(sv1.w, sv1.w);
        }
        __syncthreads();

        // ---- prefetch next chunk ----
        if (kc + 1 < NCH) {
            xv0 = xq[(kc + 1) * 8 + lkq];
            xv1 = xq[(kc + 1) * 8 + lkq + 4];
            sv0 = sq[(kc + 1) * 8 + lkq];
            sv1 = sq[(kc + 1) * 8 + lkq + 4];
        }

        // ---- compute: 32 k-steps, 3 LDS.128 + 8 FMA2 each ----
        {
            const uint32_t ap = sb + XT_OFF + buf * 8192  + (uint32_t)r0 * 4;
            const uint32_t bp = sb + BD_OFF + buf * 16384 + (uint32_t)e0 * 8;
#pragma unroll
            for (int k = 0; k < BK; k++) {
                unsigned long long a01, a23, b0, b1, b2, b3;
                lds_v2u64(ap + k * 256, a01, a23);
                lds_v2u64(bp + k * 512, b0, b1);
                lds_v2u64(bp + k * 512 + 16, b2, b3);
                fma2(acc[0][0], a01, b0); fma2(acc[0][1], a01, b1);
                fma2(acc[0][2], a01, b2); fma2(acc[0][3], a01, b3);
                fma2(acc[1][0], a23, b0); fma2(acc[1][1], a23, b1);
                fma2(acc[1][2], a23, b2); fma2(acc[1][3], a23, b3);
            }
        }
        __syncthreads();
    }

    // ---- combine sumsq partials, inv norm ----
    float* pss = (float*)(sm + PS_OFF);
    float* rowsum = (float*)(sm + RS_OFF);
    pss[lkq * 64 + lrow] = ss;
    __syncthreads();
    if (tid < TILE_M) {
        float s = ((pss[tid] + pss[64 + tid]) + pss[128 + tid]) + pss[192 + tid];
        rowsum[tid] = 1.f / fmaxf(sqrtf(s), 1e-12f);
    }
    __syncthreads();

    // ---- scale, write resonance, stash scaled rows in scratch ----
    float* scr = (float*)sm;     // [64][65]
#pragma unroll
    for (int p = 0; p < 2; p++) {
        const int ra = r0 + 2 * p;
        const int rb = ra + 1;
        const float s0 = 5.0f * rowsum[ra];
        const float s1 = 5.0f * rowsum[rb];
        float lo[4], hi[4];
#pragma unroll
        for (int j = 0; j < 4; j++) {
            unsigned long long u = acc[p][j];
            lo[j] = __uint_as_float((uint32_t)u) * s0;
            hi[j] = __uint_as_float((uint32_t)(u >> 32)) * s1;
        }
        *(float4*)(out_res + (size_t)(row0 + ra) * E_DIM + e0) =
            make_float4(lo[0], lo[1], lo[2], lo[3]);
        *(float4*)(out_res + (size_t)(row0 + rb) * E_DIM + e0) =
            make_float4(hi[0], hi[1], hi[2], hi[3]);
#pragma unroll
        for (int j = 0; j < 4; j++) {
            scr[ra * 65 + e0 + j] = lo[j];
            scr[rb * 65 + e0 + j] = hi[j];
        }
    }
    __syncthreads();

    // ---- fused top-8 + softplus (threads 0..63, one row each) ----
    if (tid < TILE_M) {
        float vals[64];
#pragma unroll
        for (int c = 0; c < 64; c++) vals[c] = scr[tid * 65 + c];
        float* wp = out_w + (size_t)(row0 + tid) * TOPK;
        float* ip = out_i + (size_t)(row0 + tid) * TOPK;
#pragma unroll
        for (int it = 0; it < TOPK; it++) {
            float best = vals[0];
            int bi = 0;
#pragma unroll
            for (int c = 1; c < 64; c++) {
                if (vals[c] > best) { best = vals[c]; bi = c; }
            }
            vals[bi] = -INFINITY;
            wp[it] = softplus_f(best);
            ip[it] = (float)bi;
        }
    }
}

extern "C" void kernel_launch(void* const* d_in, const int* in_sizes, int n_in,
                              void* d_out, int out_size)
{
    const float* x   = (const float*)d_in[0];
    const float* sig = (const float*)d_in[1];
    const int n_rows = in_sizes[0] / D_DIM;   // 16384

    float* out = (float*)d_out;
    float* out_w   = out;
    float* out_i   = out + (size_t)n_rows * TOPK;
    float* out_res = out + (size_t)n_rows * TOPK * 2;

    cudaFuncSetAttribute(router_f32x2_v3_kernel,
                         cudaFuncAttributeMaxDynamicSharedMemorySize, SMEM_DYN);

    router_f32x2_v3_kernel<<<n_rows / TILE_M, NTHREADS, SMEM_DYN>>>(
        x, sig, out_w, out_i, out_res);
}

// round 8
// speedup vs baseline: 1.8863x; 1.7111x over previous
#include <cuda_runtime.h>
#include <math.h>
#include <stdint.h>

#define D_DIM    4096
#define E_DIM    64
#define TOPK     8
#define TILE_M   128
#define BK       32
#define NCH      (D_DIM / BK)     // 128
#define NTHREADS 256

// smem layout (bytes)
// XT: [2 buf][32 k][128 rows] f32, 4-row-group XOR swizzle    -> 2*16384
// BD: [2 buf][32 k][64 e dup f32x2], pair XOR swizzle          -> 2*16384
// PS: partial sumsq [128 rows][8 slots] f32                    -> 4096
// RS: inv norm [128] f32
#define XT_OFF   0
#define XT_BUF   16384
#define BD_OFF   32768
#define BD_BUF   16384
#define PS_OFF   65536
#define RS_OFF   69632
#define SMEM_DYN 70144
// epilogue scratch (128*65*4 = 33280 B) reuses XT region

static __device__ __forceinline__ uint32_t smem_u32(const void* p) {
    uint32_t a;
    asm("{ .reg .u64 t; cvta.to.shared.u64 t, %1; cvt.u32.u64 %0, t; }" : "=r"(a) : "l"(p));
    return a;
}

static __device__ __forceinline__ void lds_v2u64(uint32_t addr,
                                                 unsigned long long& a,
                                                 unsigned long long& b) {
    asm volatile("ld.shared.v2.b64 {%0,%1}, [%2];" : "=l"(a), "=l"(b) : "r"(addr));
}

static __device__ __forceinline__ void fma2(unsigned long long& d,
                                            unsigned long long a,
                                            unsigned long long b) {
    asm("fma.rn.f32x2 %0, %1, %2, %0;" : "+l"(d) : "l"(a), "l"(b));
}

static __device__ __forceinline__ unsigned long long dupf(float f) {
    unsigned long long r;
    uint32_t u = __float_as_uint(f);
    asm("mov.b64 %0, {%1, %1};" : "=l"(r) : "r"(u));
    return r;
}

static __device__ __forceinline__ float softplus_f(float v) {
    return fmaxf(v, 0.f) + log1pf(expf(-fabsf(v)));
}

__global__ __launch_bounds__(NTHREADS, 1)
void router_f32x2_v4_kernel(const float* __restrict__ x,
                            const float* __restrict__ sig,
                            float* __restrict__ out_w,
                            float* __restrict__ out_i,
                            float* __restrict__ out_res)
{
    extern __shared__ char sm[];
    const uint32_t sb = smem_u32(sm);

    const int tid  = threadIdx.x;
    const int wid  = tid >> 5;
    const int lane = tid & 31;
    const int row0 = blockIdx.x * TILE_M;

    // compute-side coords: warp tile 64 rows x 16 experts
    const int wy = wid >> 2;           // row band (64 rows)
    const int wx = wid & 3;            // expert band (16 experts)
    const int ey = lane & 7;           // 8 row-groups (4 rows each, x2 g)
    const int ex = lane >> 3;          // 4 expert-groups (4 experts)
    const int r4a = wy * 16 + ey;      // row4 index, g=0
    const int r4b = r4a + 8;           // row4 index, g=1
    const int p0  = wx * 8 + ex * 2;   // expert-pair 0
    const int p1  = p0 + 1;            // expert-pair 1
    const int e0  = wx * 16 + ex * 4;  // first expert

    // loader coords: lanes span k (coalesced LDG, 4 lines/instr)
    const int lsub  = (tid >> 3) & 3;  // sub-row / sub-expert
    const int lkoff = tid & 7;         // float4 slot within chunk

    // acc[gp][j]: gp = g*2+p selects row pair, j selects expert
    unsigned long long acc[4][4];
#pragma unroll
    for (int a = 0; a < 4; a++)
#pragma unroll
        for (int j = 0; j < 4; j++) acc[a][j] = 0ull;

    float ss[4] = {0.f, 0.f, 0.f, 0.f};   // sumsq partials: row w*16+i*4+lsub, slot lkoff

    // prologue: chunk 0 loads (coalesced)
    float4 xv[4], sv[2];
#pragma unroll
    for (int i = 0; i < 4; i++)
        xv[i] = *((const float4*)x +
                  (size_t)(row0 + wid * 16 + i * 4 + lsub) * (D_DIM / 4) + lkoff);
#pragma unroll
    for (int i = 0; i < 2; i++)
        sv[i] = *((const float4*)sig +
                  (size_t)(wid * 8 + i * 4 + lsub) * (D_DIM / 4) + lkoff);

    for (int kc = 0; kc < NCH; kc++) {
        const int buf = kc & 1;

        // ---- store regs -> swizzled smem; fold sumsq from registers ----
        {
            float* xt = (float*)(sm + XT_OFF + buf * XT_BUF);
#pragma unroll
            for (int i = 0; i < 4; i++) {
                float4 v = xv[i];
                ss[i] = fmaf(v.x, v.x, fmaf(v.y, v.y,
                          fmaf(v.z, v.z, fmaf(v.w, v.w, ss[i]))));
                const int col4 = (wid * 4 + i) ^ lkoff;           // f(k) = (k>>2)&7 = lkoff
                const int bw = (lkoff * 4) * 128 + col4 * 4 + lsub;
                xt[bw]       = v.x;
                xt[bw + 128] = v.y;
                xt[bw + 256] = v.z;
                xt[bw + 384] = v.w;
            }
            unsigned long long* bd = (unsigned long long*)(sm + BD_OFF + buf * BD_BUF);
#pragma unroll
            for (int i = 0; i < 2; i++) {
                float4 v = sv[i];
                const int e  = wid * 8 + i * 4 + lsub;
                const int Pp = (e >> 1) ^ lkoff;                  // same f(k)
                const int bi = (lkoff * 4) * 64 + Pp * 2 + (e & 1);
                bd[bi]       = dupf(v.x);
                bd[bi + 64]  = dupf(v.y);
                bd[bi + 128] = dupf(v.z);
                bd[bi + 192] = dupf(v.w);
            }
        }
        __syncthreads();

        // ---- prefetch next chunk (coalesced) ----
        if (kc + 1 < NCH) {
#pragma unroll
            for (int i = 0; i < 4; i++)
                xv[i] = *((const float4*)x +
                          (size_t)(row0 + wid * 16 + i * 4 + lsub) * (D_DIM / 4) +
                          (kc + 1) * 8 + lkoff);
#pragma unroll
            for (int i = 0; i < 2; i++)
                sv[i] = *((const float4*)sig +
                          (size_t)(wid * 8 + i * 4 + lsub) * (D_DIM / 4) +
                          (kc + 1) * 8 + lkoff);
        }

        // ---- compute: 32 k-steps, 4 LDS.128 + 16 FMA2 each ----
        {
            const uint32_t ab = sb + XT_OFF + buf * XT_BUF;
            const uint32_t bb = sb + BD_OFF + buf * BD_BUF;
#pragma unroll
            for (int kf = 0; kf < 8; kf++) {
                const uint32_t a0o = (uint32_t)((r4a ^ kf) * 16);
                const uint32_t a1o = (uint32_t)((r4b ^ kf) * 16);
                const uint32_t b0o = (uint32_t)((p0 ^ kf) * 16);
                const uint32_t b1o = (uint32_t)((p1 ^ kf) * 16);
#pragma unroll
                for (int kj = 0; kj < 4; kj++) {
                    const uint32_t kb = (uint32_t)(kf * 4 + kj) * 512u;
                    unsigned long long a01, a23, a45, a67, b0, b1, b2, b3;
                    lds_v2u64(ab + kb + a0o, a01, a23);
                    lds_v2u64(ab + kb + a1o, a45, a67);
                    lds_v2u64(bb + kb + b0o, b0, b1);
                    lds_v2u64(bb + kb + b1o, b2, b3);
                    fma2(acc[0][0], a01, b0); fma2(acc[0][1], a01, b1);
                    fma2(acc[0][2], a01, b2); fma2(acc[0][3], a01, b3);
                    fma2(acc[1][0], a23, b0); fma2(acc[1][1], a23, b1);
                    fma2(acc[1][2], a23, b2); fma2(acc[1][3], a23, b3);
                    fma2(acc[2][0], a45, b0); fma2(acc[2][1], a45, b1);
                    fma2(acc[2][2], a45, b2); fma2(acc[2][3], a45, b3);
                    fma2(acc[3][0], a67, b0); fma2(acc[3][1], a67, b1);
                    fma2(acc[3][2], a67, b2); fma2(acc[3][3], a67, b3);
                }
            }
        }
        __syncthreads();
    }

    // ---- combine sumsq partials, inv norm ----
    float* pss = (float*)(sm + PS_OFF);
    float* rowsum = (float*)(sm + RS_OFF);
#pragma unroll
    for (int i = 0; i < 4; i++)
        pss[(wid * 16 + i * 4 + lsub) * 8 + lkoff] = ss[i];
    __syncthreads();
    if (tid < TILE_M) {
        float s = 0.f;
#pragma unroll
        for (int q = 0; q < 8; q++) s += pss[tid * 8 + q];
        rowsum[tid] = 1.f / fmaxf(sqrtf(s), 1e-12f);
    }
    __syncthreads();

    // ---- scale, write resonance, stash scaled rows in scratch ----
    float* scr = (float*)sm;      // [128][65]
#pragma unroll
    for (int g = 0; g < 2; g++) {
#pragma unroll
        for (int p = 0; p < 2; p++) {
            const int lr = wy * 64 + g * 32 + ey * 4 + 2 * p;
            const float s0 = 5.0f * rowsum[lr];
            const float s1 = 5.0f * rowsum[lr + 1];
            float lo[4], hi[4];
#pragma unroll
            for (int j = 0; j < 4; j++) {
                unsigned long long u = acc[g * 2 + p][j];
                lo[j] = __uint_as_float((uint32_t)u) * s0;
                hi[j] = __uint_as_float((uint32_t)(u >> 32)) * s1;
            }
            *(float4*)(out_res + (size_t)(row0 + lr) * E_DIM + e0) =
                make_float4(lo[0], lo[1], lo[2], lo[3]);
            *(float4*)(out_res + (size_t)(row0 + lr + 1) * E_DIM + e0) =
                make_float4(hi[0], hi[1], hi[2], hi[3]);
#pragma unroll
            for (int j = 0; j < 4; j++) {
                scr[lr * 65 + e0 + j]       = lo[j];
                scr[(lr + 1) * 65 + e0 + j] = hi[j];
            }
        }
    }
    __syncthreads();

    // ---- fused top-8 + softplus (threads 0..127, one row each) ----
    if (tid < TILE_M) {
        float vals[64];
#pragma unroll
        for (int c = 0; c < 64; c++) vals[c] = scr[tid * 65 + c];
        float* wp = out_w + (size_t)(row0 + tid) * TOPK;
        float* ip = out_i + (size_t)(row0 + tid) * TOPK;
#pragma unroll
        for (int it = 0; it < TOPK; it++) {
            float best = vals[0];
            int bi = 0;
#pragma unroll
            for (int c = 1; c < 64; c++) {
                if (vals[c] > best) { best = vals[c]; bi = c; }
            }
            vals[bi] = -INFINITY;
            wp[it] = softplus_f(best);
            ip[it] = (float)bi;
        }
    }
}

extern "C" void kernel_launch(void* const* d_in, const int* in_sizes, int n_in,
                              void* d_out, int out_size)
{
    const float* x   = (const float*)d_in[0];
    const float* sig = (const float*)d_in[1];
    const int n_rows = in_sizes[0] / D_DIM;   // 16384

    float* out = (float*)d_out;
    float* out_w   = out;
    float* out_i   = out + (size_t)n_rows * TOPK;
    float* out_res = out + (size_t)n_rows * TOPK * 2;

    cudaFuncSetAttribute(router_f32x2_v4_kernel,
                         cudaFuncAttributeMaxDynamicSharedMemorySize, SMEM_DYN);

    router_f32x2_v4_kernel<<<n_rows / TILE_M, NTHREADS, SMEM_DYN>>>(
        x, sig, out_w, out_i, out_res);
}